// round 9
// baseline (speedup 1.0000x reference)
#include <cuda_runtime.h>
#include <math.h>

// ---------------------------------------------------------------------------
// EnhancedContrastiveLoss — v9: v8 minus the broken parallel klab.
// Core: symmetric-half tf32 mma.sync + 3-stage cp.async, branchless
// poisoned-diagonal epilogue, diag-last ordering, 16-thread/row krow.
// klab reverted to the SAFE single-CTA global dtype detector (v6-proven).
// ---------------------------------------------------------------------------

namespace {
constexpr int   NB   = 8192;
constexpr int   ND   = 256;
constexpr float TEMP = 0.07f;
constexpr float MRG  = 0.2f;
constexpr float NEGINF = -1e30f;
constexpr float CEXP = 20.609929059847869f;   // log2(e)/TEMP

constexpr int NBLK  = NB / 128;               // 64 row-blocks
constexpr int NOFF  = NBLK * (NBLK - 1) / 2;  // 2016 off-diagonal pairs
constexpr int NPAIR = NOFF + NBLK;            // 2080 CTAs
constexpr int NTHR  = 256;                    // 8 warps: 2(M) x 4(N)
constexpr int OST   = 36;                     // operand smem row stride (floats)
constexpr int DST   = 129;                    // D-tile smem row stride (floats)
constexpr int NSTAGE = 3;
constexpr int RED_BLOCKS = 512;

// dynamic smem layout (bytes)
constexpr int SM_OPA  = 0;                        // 3 x 18432 = 55296
constexpr int SM_OPB  = 55296;                    // 3 x 18432 = 55296
constexpr int SM_LABI = 110592;                   // 128 int
constexpr int SM_LABJ = 111104;                   // 128 int
constexpr int SMEM_TOTAL = 111616;
// post-GEMM overlays: D tile 128x129 f32 @0 (66048 B), staging @66560 (12288 B)
constexpr int SM_STG  = 66560;
}

__device__ float g_en[NB * ND];                // normalized, tf32-rounded
__device__ int   g_lab[NB];
__device__ float g_part[6 * NBLK * NB];        // [q][slot][row]
__device__ float g_blk[RED_BLOCKS * 5];

// ----------------------------- helpers ------------------------------------
__device__ __forceinline__ unsigned smem_u32(const void* p) {
    unsigned a;
    asm("{ .reg .u64 t; cvta.to.shared.u64 t, %1; cvt.u32.u64 %0, t; }" : "=r"(a) : "l"(p));
    return a;
}
__device__ __forceinline__ void cpasync16(unsigned dst, const void* src) {
    asm volatile("cp.async.cg.shared.global [%0], [%1], 16;" :: "r"(dst), "l"(src) : "memory");
}
#define CP_COMMIT() asm volatile("cp.async.commit_group;" ::: "memory")
#define CP_WAIT0()  asm volatile("cp.async.wait_group 0;"  ::: "memory")
#define CP_WAIT1()  asm volatile("cp.async.wait_group 1;"  ::: "memory")

__device__ __forceinline__ void mma_tf32(float c[4], const unsigned a[4], const unsigned b[2]) {
    asm volatile(
        "mma.sync.aligned.m16n8k8.row.col.f32.tf32.tf32.f32 "
        "{%0,%1,%2,%3}, {%4,%5,%6,%7}, {%8,%9}, {%0,%1,%2,%3};"
        : "+f"(c[0]), "+f"(c[1]), "+f"(c[2]), "+f"(c[3])
        : "r"(a[0]), "r"(a[1]), "r"(a[2]), "r"(a[3]), "r"(b[0]), "r"(b[1]));
}

__device__ __forceinline__ float ex2f(float x) {
    float y; asm("ex2.approx.f32 %0, %1;" : "=f"(y) : "f"(x)); return y;
}
__device__ __forceinline__ void ins3(float& t0, float& t1, float& t2, float x) {
    float m;
    m = fmaxf(t0, x); x = fminf(t0, x); t0 = m;
    m = fmaxf(t1, x); x = fminf(t1, x); t1 = m;
    t2 = fmaxf(t2, x);
}

// ---------------------------------------------------------------------------
// Kernel 0: label dtype normalize — SAFE single-CTA global detection.
// Reads only the first NB int32 words (in-bounds for both int32 and int64
// buffers). int64 labels in [0,512) => all odd words zero; int32 labels make
// some odd word nonzero with overwhelming probability.
// ---------------------------------------------------------------------------
__global__ void klab(const int* __restrict__ lab32) {
    __shared__ int s_nz;
    if (threadIdx.x == 0) s_nz = 0;
    __syncthreads();
    int acc = 0;
    for (int i = threadIdx.x; i < NB / 2; i += blockDim.x) acc |= lab32[2 * i + 1];
    if (acc) atomicOr(&s_nz, 1);
    __syncthreads();
    const bool is64 = (s_nz == 0);
    for (int i = threadIdx.x; i < NB; i += blockDim.x)
        g_lab[i] = is64 ? lab32[2 * i] : lab32[i];
}

// ---------------------------------------------------------------------------
// Kernel 1: L2 normalize + round-to-nearest-tf32
// ---------------------------------------------------------------------------
__global__ void knorm(const float* __restrict__ emb) {
    int gw   = (blockIdx.x * blockDim.x + threadIdx.x) >> 5;
    int lane = threadIdx.x & 31;
    if (gw >= NB) return;
    const float4* src = reinterpret_cast<const float4*>(emb + (size_t)gw * ND);
    float4 v0 = src[lane * 2];
    float4 v1 = src[lane * 2 + 1];
    float ss = v0.x*v0.x + v0.y*v0.y + v0.z*v0.z + v0.w*v0.w
             + v1.x*v1.x + v1.y*v1.y + v1.z*v1.z + v1.w*v1.w;
    #pragma unroll
    for (int o = 16; o > 0; o >>= 1) ss += __shfl_xor_sync(0xffffffffu, ss, o);
    float inv = 1.0f / fmaxf(sqrtf(ss), 1e-12f);
    float f[8] = {v0.x*inv, v0.y*inv, v0.z*inv, v0.w*inv,
                  v1.x*inv, v1.y*inv, v1.z*inv, v1.w*inv};
    #pragma unroll
    for (int i = 0; i < 8; i++) {
        unsigned b;
        asm("cvt.rna.tf32.f32 %0, %1;" : "=r"(b) : "f"(f[i]));
        f[i] = __uint_as_float(b);
    }
    float4* dst = reinterpret_cast<float4*>(g_en + (size_t)gw * ND);
    dst[lane * 2]     = make_float4(f[0], f[1], f[2], f[3]);
    dst[lane * 2 + 1] = make_float4(f[4], f[5], f[6], f[7]);
}

// ---------------------------------------------------------------------------
// Kernel 2: symmetric-half tf32 GEMM + branchless two-view fused epilogue.
// Block order: 2016 off-diagonal pairs first, 64 cheap diagonal blocks last.
// ---------------------------------------------------------------------------
__global__ void __launch_bounds__(NTHR, 2) kmain() {
    extern __shared__ char smem[];
    float* OpA  = (float*)(smem + SM_OPA);
    float* OpB  = (float*)(smem + SM_OPB);
    float* Ds   = (float*)smem;                 // overlays operands post-GEMM
    float* stg  = (float*)(smem + SM_STG);
    int*   labI = (int*)(smem + SM_LABI);
    int*   labJ = (int*)(smem + SM_LABJ);
    const unsigned sbA = smem_u32(OpA), sbB = smem_u32(OpB);

    const int tid   = threadIdx.x;
    const int lane  = tid & 31;
    const int wid   = tid >> 5;
    const int warpM = wid >> 2;          // 0..1
    const int warpN = wid & 3;           // 0..3
    const int qrow  = lane >> 2;         // 0..7
    const int qcol  = lane & 3;          // 0..3

    // block id -> (I, J): off-diagonals first (I < J), diagonals last
    int I, J;
    if (blockIdx.x < NOFF) {
        int i = 0, rem = blockIdx.x;
        while (rem >= NBLK - 1 - i) { rem -= NBLK - 1 - i; i++; }
        I = i; J = i + 1 + rem;
    } else {
        I = J = blockIdx.x - NOFF;
    }
    const int rowI = I * 128, rowJ = J * 128;
    const bool diag = (I == J);

    // labels into smem
    if (tid < 128) labI[tid] = g_lab[rowI + tid];
    else           labJ[tid - 128] = g_lab[rowJ + tid - 128];

    // chunk issue into stage g%3 (diag: A only, B aliases A)
    auto issue = [&](int g) {
        const int stage = g % NSTAGE;
        const int kc = g * 32;
        #pragma unroll
        for (int q = 0; q < 4; q++) {
            int idx = tid + q * NTHR;        // 0..1023
            int r = idx >> 3, f = (idx & 7) * 4;
            unsigned off = (unsigned)((stage * 128 + r) * OST + f) * 4u;
            cpasync16(sbA + off, g_en + (size_t)(rowI + r) * ND + kc + f);
            if (!diag)
                cpasync16(sbB + off, g_en + (size_t)(rowJ + r) * ND + kc + f);
        }
        CP_COMMIT();
    };

    float acc[4][4][4];
    #pragma unroll
    for (int i = 0; i < 4; i++)
        #pragma unroll
        for (int j = 0; j < 4; j++)
            #pragma unroll
            for (int c = 0; c < 4; c++) acc[i][j][c] = 0.f;

    issue(0); issue(1);

    for (int g = 0; g < 8; g++) {
        if (g < 7) CP_WAIT1();
        else       CP_WAIT0();
        __syncthreads();                     // all warps done with chunk g-1
        if (g + 2 < 8) issue(g + 2);

        const int stage = g % NSTAGE;
        const float* Apan = OpA + stage * 128 * OST;
        const float* Bpan = diag ? Apan : OpB + stage * 128 * OST;
        #pragma unroll
        for (int ks = 0; ks < 4; ks++) {
            const int kb = ks * 8;
            unsigned a[4][4], b[4][2];
            #pragma unroll
            for (int i = 0; i < 4; i++) {
                const float* ap = Apan + (size_t)(warpM * 64 + i * 16 + qrow) * OST + kb + qcol;
                a[i][0] = __float_as_uint(ap[0]);
                a[i][1] = __float_as_uint(ap[8 * OST]);
                a[i][2] = __float_as_uint(ap[4]);
                a[i][3] = __float_as_uint(ap[8 * OST + 4]);
            }
            #pragma unroll
            for (int j = 0; j < 4; j++) {
                const float* bp = Bpan + (size_t)(warpN * 32 + j * 8 + qrow) * OST + kb + qcol;
                b[j][0] = __float_as_uint(bp[0]);
                b[j][1] = __float_as_uint(bp[4]);
            }
            #pragma unroll
            for (int i = 0; i < 4; i++)
                #pragma unroll
                for (int j = 0; j < 4; j++)
                    mma_tf32(acc[i][j], a[i], b[j]);
        }
    }
    __syncthreads();                         // GEMM done; operand smem dead

    // ---- stage D into smem (stride 129) ----
    #pragma unroll
    for (int i = 0; i < 4; i++) {
        #pragma unroll
        for (int j = 0; j < 4; j++) {
            const int rl0 = warpM * 64 + i * 16 + qrow;
            const int cl0 = warpN * 32 + j * 8 + 2 * qcol;
            Ds[(size_t)rl0 * DST + cl0]           = acc[i][j][0];
            Ds[(size_t)rl0 * DST + cl0 + 1]       = acc[i][j][1];
            Ds[(size_t)(rl0 + 8) * DST + cl0]     = acc[i][j][2];
            Ds[(size_t)(rl0 + 8) * DST + cl0 + 1] = acc[i][j][3];
        }
    }
    __syncthreads();
    // poison the self-similarity diagonal so the epilogue needs no branch:
    // d=-1e30 -> E=0 (no sA/sP effect), max candidates -1e30==NEGINF sentinel
    if (diag && tid < 128) Ds[(size_t)tid * DST + tid] = NEGINF;
    __syncthreads();

    // ---- branchless task-parallel epilogue: 512 tasks = {view, half, idx} ----
    const int rounds = diag ? 1 : 2;
    for (int rr = 0; rr < rounds; rr++) {
        const int tau  = tid + rr * 256;
        const int view = tau >> 8;
        const int half = (tau >> 7) & 1;
        const int idx  = tau & 127;
        float sA = 0.f, sP = 0.f, pm = NEGINF;
        float t0 = NEGINF, t1 = NEGINF, t2 = NEGINF;
        if (view == 0) {
            const int lr = labI[idx];
            const float* dr = Ds + (size_t)idx * DST + half * 64;
            const int* lc = labJ + half * 64;
            #pragma unroll 4
            for (int c = 0; c < 64; c++) {
                float d = dr[c];
                float E = ex2f(d * CEXP);
                bool same = (lr == lc[c]);
                sA += E;
                sP += same ? E : 0.f;
                pm = fmaxf(pm, same ? d : NEGINF);
                ins3(t0, t1, t2, same ? NEGINF : d);
            }
        } else {
            const int lcv = labJ[idx];
            const float* dc = Ds + (size_t)(half * 64) * DST + idx;
            const int* lrr = labI + half * 64;
            #pragma unroll 4
            for (int r = 0; r < 64; r++) {
                float d = dc[(size_t)r * DST];
                float E = ex2f(d * CEXP);
                bool same = (lcv == lrr[r]);
                sA += E;
                sP += same ? E : 0.f;
                pm = fmaxf(pm, same ? d : NEGINF);
                ins3(t0, t1, t2, same ? NEGINF : d);
            }
        }
        float* p = stg + (size_t)tau * 6;
        p[0] = sA; p[1] = sP; p[2] = pm; p[3] = t0; p[4] = t1; p[5] = t2;
    }
    __syncthreads();

    // ---- merge halves and write g_part ----
    if (tid < 128 || !diag) {
        const int view = tid >> 7;
        const int idx  = tid & 127;
        const float* p0 = stg + (size_t)(view * 256 + idx) * 6;
        const float* p1 = p0 + 128 * 6;
        float sA = p0[0] + p1[0];
        float sP = p0[1] + p1[1];
        float pm = fmaxf(p0[2], p1[2]);
        float t0 = p0[3], t1 = p0[4], t2 = p0[5];
        ins3(t0, t1, t2, p1[3]); ins3(t0, t1, t2, p1[4]); ins3(t0, t1, t2, p1[5]);
        const int slot = view ? I : J;
        const int grow = (view ? rowJ : rowI) + idx;
        g_part[(size_t)(0 * NBLK + slot) * NB + grow] = sA;
        g_part[(size_t)(1 * NBLK + slot) * NB + grow] = sP;
        g_part[(size_t)(2 * NBLK + slot) * NB + grow] = pm;
        g_part[(size_t)(3 * NBLK + slot) * NB + grow] = t0;
        g_part[(size_t)(4 * NBLK + slot) * NB + grow] = t1;
        g_part[(size_t)(5 * NBLK + slot) * NB + grow] = t2;
    }
}

// ---------------------------------------------------------------------------
// Kernel 3: per-row merge of 64 slot partials (16 threads/row) + loss terms.
// Grid 512 x 256: gid>>4 = row, gid&15 = slot slice of 4.
// ---------------------------------------------------------------------------
__global__ void krow() {
    const int gid = blockIdx.x * blockDim.x + threadIdx.x;
    const int row = gid >> 4;
    const int sl  = (gid & 15) * 4;
    float sA = 0.f, sP = 0.f, pm = NEGINF;
    float t0 = NEGINF, t1 = NEGINF, t2 = NEGINF;
    #pragma unroll
    for (int s = 0; s < 4; s++) {
        const int slot = sl + s;
        sA += g_part[(size_t)(0 * NBLK + slot) * NB + row];
        sP += g_part[(size_t)(1 * NBLK + slot) * NB + row];
        pm  = fmaxf(pm, g_part[(size_t)(2 * NBLK + slot) * NB + row]);
        ins3(t0, t1, t2, g_part[(size_t)(3 * NBLK + slot) * NB + row]);
        ins3(t0, t1, t2, g_part[(size_t)(4 * NBLK + slot) * NB + row]);
        ins3(t0, t1, t2, g_part[(size_t)(5 * NBLK + slot) * NB + row]);
    }
    #pragma unroll
    for (int o = 1; o <= 8; o <<= 1) {
        sA += __shfl_xor_sync(0xffffffffu, sA, o);
        sP += __shfl_xor_sync(0xffffffffu, sP, o);
        pm  = fmaxf(pm, __shfl_xor_sync(0xffffffffu, pm, o));
        float o0 = __shfl_xor_sync(0xffffffffu, t0, o);
        float o1 = __shfl_xor_sync(0xffffffffu, t1, o);
        float o2 = __shfl_xor_sync(0xffffffffu, t2, o);
        ins3(t0, t1, t2, o0); ins3(t0, t1, t2, o1); ins3(t0, t1, t2, o2);
    }

    float basic = 0.f, h = 0.f, m = 0.f, hp = 0.f, v = 0.f;
    if ((threadIdx.x & 15) == 0 && pm > -1e29f) {
        hp = 1.f;
        basic = -logf(sP / (sA + 1e-10f) + 1e-10f);
        float pms   = pm * (1.f / TEMP);
        float mean3 = (t0 + t1 + t2) * (1.f / (3.f * TEMP));
        h = fmaxf(mean3 - pms + MRG, 0.f);
        if (t0 > -1e29f) {
            v = 1.f;
            m = fmaxf(t0 * (1.f / TEMP) - pms + MRG, 0.f);
        }
    }

    __shared__ float red[5][8];
    float vals[5] = {basic, h, m, hp, v};
    int lane = threadIdx.x & 31, warp = threadIdx.x >> 5;
    #pragma unroll
    for (int q = 0; q < 5; q++) {
        float x = vals[q];
        #pragma unroll
        for (int o = 16; o > 0; o >>= 1) x += __shfl_xor_sync(0xffffffffu, x, o);
        if (lane == 0) red[q][warp] = x;
    }
    __syncthreads();
    if (warp == 0 && lane == 0) {
        #pragma unroll
        for (int q = 0; q < 5; q++) {
            float x = 0.f;
            #pragma unroll
            for (int w = 0; w < 8; w++) x += red[q][w];
            g_blk[blockIdx.x * 5 + q] = x;
        }
    }
}

// ---------------------------------------------------------------------------
// Kernel 4: final scalar.
// ---------------------------------------------------------------------------
__global__ void kfin(float* __restrict__ out, int n) {
    int lane = threadIdx.x;   // 32 threads
    float acc[5];
    #pragma unroll
    for (int q = 0; q < 5; q++) {
        float x = 0.f;
        for (int i = lane; i < RED_BLOCKS; i += 32) x += g_blk[i * 5 + q];
        #pragma unroll
        for (int o = 16; o > 0; o >>= 1) x += __shfl_xor_sync(0xffffffffu, x, o);
        acc[q] = x;
    }
    float Bv = acc[0], Hv = acc[1], Mv = acc[2], HP = acc[3], V = acc[4];
    float n_hp = fmaxf(HP, 1.f);
    float n_v  = fmaxf(V, 1.f);
    float margin_loss = (V > 0.f) ? (Mv / n_v) : 0.f;
    float total = Bv / n_hp + 0.5f * (Hv / n_hp) + 0.1f * margin_loss;
    for (int i = lane; i < n; i += 32) out[i] = total;
}

// ---------------------------------------------------------------------------
extern "C" void kernel_launch(void* const* d_in, const int* in_sizes, int n_in,
                              void* d_out, int out_size) {
    const float* emb   = (const float*)d_in[0];
    const int*   lab32 = (const int*)d_in[1];
    (void)in_sizes; (void)n_in;

    cudaFuncSetAttribute(kmain, cudaFuncAttributeMaxDynamicSharedMemorySize, SMEM_TOTAL);

    klab<<<1, 256>>>(lab32);
    knorm<<<NB * 32 / 256, 256>>>(emb);
    kmain<<<NPAIR, NTHR, SMEM_TOTAL>>>();
    krow<<<RED_BLOCKS, 256>>>();
    kfin<<<1, 32>>>((float*)d_out, out_size);
}

// round 10
// speedup vs baseline: 1.4867x; 1.4867x over previous
#include <cuda_runtime.h>
#include <math.h>

// ---------------------------------------------------------------------------
// EnhancedContrastiveLoss — v10: v6 core restored exactly (symmetric-half
// tf32 mma.sync, 3-stage cp.async, branchy epilogue, v6 krow/klab), with the
// epilogue simplified to v5's direct full-row/full-col form (no smem staging,
// one fewer barrier, no merge pass, lower register footprint).
// ---------------------------------------------------------------------------

namespace {
constexpr int   NB   = 8192;
constexpr int   ND   = 256;
constexpr float TEMP = 0.07f;
constexpr float MRG  = 0.2f;
constexpr float NEGINF = -1e30f;
constexpr float CEXP = 20.609929059847869f;   // log2(e)/TEMP

constexpr int NBLK  = NB / 128;               // 64 row-blocks
constexpr int NPAIR = NBLK * (NBLK + 1) / 2;  // 2080 CTAs
constexpr int NTHR  = 256;                    // 8 warps: 2(M) x 4(N)
constexpr int OST   = 36;                     // operand smem row stride (floats)
constexpr int DST   = 129;                    // D-tile smem row stride (floats)
constexpr int NSTAGE = 3;
constexpr int RED_BLOCKS = 256;

// dynamic smem layout (bytes)
constexpr int SM_OPA  = 0;                        // 3 x 18432 = 55296
constexpr int SM_OPB  = 55296;                    // 3 x 18432 = 55296
constexpr int SM_LABI = 110592;                   // 128 int
constexpr int SM_LABJ = 111104;                   // 128 int
constexpr int SMEM_TOTAL = 111616;
// post-GEMM overlay: D tile 128x129 f32 @0 (66048 B)
}

__device__ float g_en[NB * ND];                // normalized, tf32-rounded
__device__ int   g_lab[NB];
__device__ float g_part[6 * NBLK * NB];        // [q][slot][row]
__device__ float g_blk[RED_BLOCKS * 5];

// ----------------------------- helpers ------------------------------------
__device__ __forceinline__ unsigned smem_u32(const void* p) {
    unsigned a;
    asm("{ .reg .u64 t; cvta.to.shared.u64 t, %1; cvt.u32.u64 %0, t; }" : "=r"(a) : "l"(p));
    return a;
}
__device__ __forceinline__ void cpasync16(unsigned dst, const void* src) {
    asm volatile("cp.async.cg.shared.global [%0], [%1], 16;" :: "r"(dst), "l"(src) : "memory");
}
#define CP_COMMIT() asm volatile("cp.async.commit_group;" ::: "memory")
#define CP_WAIT0()  asm volatile("cp.async.wait_group 0;"  ::: "memory")
#define CP_WAIT1()  asm volatile("cp.async.wait_group 1;"  ::: "memory")

__device__ __forceinline__ void mma_tf32(float c[4], const unsigned a[4], const unsigned b[2]) {
    asm volatile(
        "mma.sync.aligned.m16n8k8.row.col.f32.tf32.tf32.f32 "
        "{%0,%1,%2,%3}, {%4,%5,%6,%7}, {%8,%9}, {%0,%1,%2,%3};"
        : "+f"(c[0]), "+f"(c[1]), "+f"(c[2]), "+f"(c[3])
        : "r"(a[0]), "r"(a[1]), "r"(a[2]), "r"(a[3]), "r"(b[0]), "r"(b[1]));
}

__device__ __forceinline__ float ex2f(float x) {
    float y; asm("ex2.approx.f32 %0, %1;" : "=f"(y) : "f"(x)); return y;
}
__device__ __forceinline__ void ins3(float& t0, float& t1, float& t2, float x) {
    float m;
    m = fmaxf(t0, x); x = fminf(t0, x); t0 = m;
    m = fmaxf(t1, x); x = fminf(t1, x); t1 = m;
    t2 = fmaxf(t2, x);
}

// ---------------------------------------------------------------------------
// Kernel 0: label dtype normalize — SAFE single-CTA global detection
// (reads only the first NB int32 words; in-bounds for both dtypes).
// ---------------------------------------------------------------------------
__global__ void klab(const int* __restrict__ lab32) {
    __shared__ int s_nz;
    if (threadIdx.x == 0) s_nz = 0;
    __syncthreads();
    int acc = 0;
    for (int i = threadIdx.x; i < NB / 2; i += blockDim.x) acc |= lab32[2 * i + 1];
    if (acc) atomicOr(&s_nz, 1);
    __syncthreads();
    const bool is64 = (s_nz == 0);
    for (int i = threadIdx.x; i < NB; i += blockDim.x)
        g_lab[i] = is64 ? lab32[2 * i] : lab32[i];
}

// ---------------------------------------------------------------------------
// Kernel 1: L2 normalize + round-to-nearest-tf32
// ---------------------------------------------------------------------------
__global__ void knorm(const float* __restrict__ emb) {
    int gw   = (blockIdx.x * blockDim.x + threadIdx.x) >> 5;
    int lane = threadIdx.x & 31;
    if (gw >= NB) return;
    const float4* src = reinterpret_cast<const float4*>(emb + (size_t)gw * ND);
    float4 v0 = src[lane * 2];
    float4 v1 = src[lane * 2 + 1];
    float ss = v0.x*v0.x + v0.y*v0.y + v0.z*v0.z + v0.w*v0.w
             + v1.x*v1.x + v1.y*v1.y + v1.z*v1.z + v1.w*v1.w;
    #pragma unroll
    for (int o = 16; o > 0; o >>= 1) ss += __shfl_xor_sync(0xffffffffu, ss, o);
    float inv = 1.0f / fmaxf(sqrtf(ss), 1e-12f);
    float f[8] = {v0.x*inv, v0.y*inv, v0.z*inv, v0.w*inv,
                  v1.x*inv, v1.y*inv, v1.z*inv, v1.w*inv};
    #pragma unroll
    for (int i = 0; i < 8; i++) {
        unsigned b;
        asm("cvt.rna.tf32.f32 %0, %1;" : "=r"(b) : "f"(f[i]));
        f[i] = __uint_as_float(b);
    }
    float4* dst = reinterpret_cast<float4*>(g_en + (size_t)gw * ND);
    dst[lane * 2]     = make_float4(f[0], f[1], f[2], f[3]);
    dst[lane * 2 + 1] = make_float4(f[4], f[5], f[6], f[7]);
}

// ---------------------------------------------------------------------------
// Kernel 2: symmetric-half tf32 GEMM + two-view fused epilogue (direct).
// Grid: 2080 CTAs (one 128x128 block (I,J), I<=J each). 256 threads.
// Both operands streamed, 3-stage pipeline, one __syncthreads per chunk.
// ---------------------------------------------------------------------------
__global__ void __launch_bounds__(NTHR, 2) kmain() {
    extern __shared__ char smem[];
    float* OpA  = (float*)(smem + SM_OPA);
    float* OpB  = (float*)(smem + SM_OPB);
    float* Ds   = (float*)smem;                 // overlays operands post-GEMM
    int*   labI = (int*)(smem + SM_LABI);
    int*   labJ = (int*)(smem + SM_LABJ);
    const unsigned sbA = smem_u32(OpA), sbB = smem_u32(OpB);

    const int tid   = threadIdx.x;
    const int lane  = tid & 31;
    const int wid   = tid >> 5;
    const int warpM = wid >> 2;          // 0..1
    const int warpN = wid & 3;           // 0..3
    const int qrow  = lane >> 2;         // 0..7
    const int qcol  = lane & 3;          // 0..3

    // map linear block id -> (I, J), I <= J  (v6 ordering)
    int I = 0, rem = blockIdx.x;
    while (rem >= NBLK - I) { rem -= NBLK - I; I++; }
    const int J = I + rem;
    const int rowI = I * 128, rowJ = J * 128;
    const bool diag = (I == J);

    // labels into smem
    if (tid < 128) labI[tid] = g_lab[rowI + tid];
    else           labJ[tid - 128] = g_lab[rowJ + tid - 128];

    // chunk issue into stage g%3 (diag: A only, B aliases A)
    auto issue = [&](int g) {
        const int stage = g % NSTAGE;
        const int kc = g * 32;
        #pragma unroll
        for (int q = 0; q < 4; q++) {
            int idx = tid + q * NTHR;        // 0..1023
            int r = idx >> 3, f = (idx & 7) * 4;
            unsigned off = (unsigned)((stage * 128 + r) * OST + f) * 4u;
            cpasync16(sbA + off, g_en + (size_t)(rowI + r) * ND + kc + f);
            if (!diag)
                cpasync16(sbB + off, g_en + (size_t)(rowJ + r) * ND + kc + f);
        }
        CP_COMMIT();
    };

    float acc[4][4][4];
    #pragma unroll
    for (int i = 0; i < 4; i++)
        #pragma unroll
        for (int j = 0; j < 4; j++)
            #pragma unroll
            for (int c = 0; c < 4; c++) acc[i][j][c] = 0.f;

    issue(0); issue(1);

    for (int g = 0; g < 8; g++) {
        if (g < 7) CP_WAIT1();
        else       CP_WAIT0();
        __syncthreads();                     // all warps done with chunk g-1
        if (g + 2 < 8) issue(g + 2);

        const int stage = g % NSTAGE;
        const float* Apan = OpA + stage * 128 * OST;
        const float* Bpan = diag ? Apan : OpB + stage * 128 * OST;
        #pragma unroll
        for (int ks = 0; ks < 4; ks++) {
            const int kb = ks * 8;
            unsigned a[4][4], b[4][2];
            #pragma unroll
            for (int i = 0; i < 4; i++) {
                const float* ap = Apan + (size_t)(warpM * 64 + i * 16 + qrow) * OST + kb + qcol;
                a[i][0] = __float_as_uint(ap[0]);
                a[i][1] = __float_as_uint(ap[8 * OST]);
                a[i][2] = __float_as_uint(ap[4]);
                a[i][3] = __float_as_uint(ap[8 * OST + 4]);
            }
            #pragma unroll
            for (int j = 0; j < 4; j++) {
                const float* bp = Bpan + (size_t)(warpN * 32 + j * 8 + qrow) * OST + kb + qcol;
                b[j][0] = __float_as_uint(bp[0]);
                b[j][1] = __float_as_uint(bp[4]);
            }
            #pragma unroll
            for (int i = 0; i < 4; i++)
                #pragma unroll
                for (int j = 0; j < 4; j++)
                    mma_tf32(acc[i][j], a[i], b[j]);
        }
    }
    __syncthreads();                         // GEMM done; operand smem now dead

    // ---- stage D into smem (stride 129) ----
    #pragma unroll
    for (int i = 0; i < 4; i++) {
        #pragma unroll
        for (int j = 0; j < 4; j++) {
            const int rl0 = warpM * 64 + i * 16 + qrow;
            const int cl0 = warpN * 32 + j * 8 + 2 * qcol;
            Ds[(size_t)rl0 * DST + cl0]           = acc[i][j][0];
            Ds[(size_t)rl0 * DST + cl0 + 1]       = acc[i][j][1];
            Ds[(size_t)(rl0 + 8) * DST + cl0]     = acc[i][j][2];
            Ds[(size_t)(rl0 + 8) * DST + cl0 + 1] = acc[i][j][3];
        }
    }
    __syncthreads();

    // ---- direct two-view epilogue (v5 form): 0-127 row view, 128-255 col view
    if (tid < 128) {
        const int rl = tid, grow = rowI + rl;
        const int lr = labI[rl];
        const float* drow = Ds + (size_t)rl * DST;
        float sA = 0.f, sP = 0.f, pm = NEGINF;
        float t0 = NEGINF, t1 = NEGINF, t2 = NEGINF;
        #pragma unroll 4
        for (int c = 0; c < 128; c++) {
            float d = drow[c];
            if (!(diag && c == rl)) {
                float E = ex2f(d * CEXP);
                sA += E;
                if (lr == labJ[c]) { sP += E; pm = fmaxf(pm, d); }
                else ins3(t0, t1, t2, d);
            }
        }
        g_part[(size_t)(0 * NBLK + J) * NB + grow] = sA;
        g_part[(size_t)(1 * NBLK + J) * NB + grow] = sP;
        g_part[(size_t)(2 * NBLK + J) * NB + grow] = pm;
        g_part[(size_t)(3 * NBLK + J) * NB + grow] = t0;
        g_part[(size_t)(4 * NBLK + J) * NB + grow] = t1;
        g_part[(size_t)(5 * NBLK + J) * NB + grow] = t2;
    } else if (!diag) {
        const int cl = tid - 128, gcol = rowJ + cl;
        const int lc = labJ[cl];
        float sA = 0.f, sP = 0.f, pm = NEGINF;
        float t0 = NEGINF, t1 = NEGINF, t2 = NEGINF;
        #pragma unroll 4
        for (int r = 0; r < 128; r++) {
            float d = Ds[(size_t)r * DST + cl];
            float E = ex2f(d * CEXP);
            sA += E;
            if (lc == labI[r]) { sP += E; pm = fmaxf(pm, d); }
            else ins3(t0, t1, t2, d);
        }
        g_part[(size_t)(0 * NBLK + I) * NB + gcol] = sA;
        g_part[(size_t)(1 * NBLK + I) * NB + gcol] = sP;
        g_part[(size_t)(2 * NBLK + I) * NB + gcol] = pm;
        g_part[(size_t)(3 * NBLK + I) * NB + gcol] = t0;
        g_part[(size_t)(4 * NBLK + I) * NB + gcol] = t1;
        g_part[(size_t)(5 * NBLK + I) * NB + gcol] = t2;
    }
}

// ---------------------------------------------------------------------------
// Kernel 3: per-row merge of 64 slot partials (8 threads/row) + loss terms.
// Grid 256 x 256: gid>>3 = row, gid&7 = slot slice of 8.   (v6-proven)
// ---------------------------------------------------------------------------
__global__ void krow() {
    const int gid = blockIdx.x * blockDim.x + threadIdx.x;
    const int row = gid >> 3;
    const int sl  = (gid & 7) * 8;
    float sA = 0.f, sP = 0.f, pm = NEGINF;
    float t0 = NEGINF, t1 = NEGINF, t2 = NEGINF;
    #pragma unroll
    for (int s = 0; s < 8; s++) {
        const int slot = sl + s;
        sA += g_part[(size_t)(0 * NBLK + slot) * NB + row];
        sP += g_part[(size_t)(1 * NBLK + slot) * NB + row];
        pm  = fmaxf(pm, g_part[(size_t)(2 * NBLK + slot) * NB + row]);
        ins3(t0, t1, t2, g_part[(size_t)(3 * NBLK + slot) * NB + row]);
        ins3(t0, t1, t2, g_part[(size_t)(4 * NBLK + slot) * NB + row]);
        ins3(t0, t1, t2, g_part[(size_t)(5 * NBLK + slot) * NB + row]);
    }
    #pragma unroll
    for (int o = 1; o <= 4; o <<= 1) {
        sA += __shfl_xor_sync(0xffffffffu, sA, o);
        sP += __shfl_xor_sync(0xffffffffu, sP, o);
        pm  = fmaxf(pm, __shfl_xor_sync(0xffffffffu, pm, o));
        float o0 = __shfl_xor_sync(0xffffffffu, t0, o);
        float o1 = __shfl_xor_sync(0xffffffffu, t1, o);
        float o2 = __shfl_xor_sync(0xffffffffu, t2, o);
        ins3(t0, t1, t2, o0); ins3(t0, t1, t2, o1); ins3(t0, t1, t2, o2);
    }

    float basic = 0.f, h = 0.f, m = 0.f, hp = 0.f, v = 0.f;
    if ((threadIdx.x & 7) == 0 && pm > -1e29f) {
        hp = 1.f;
        basic = -logf(sP / (sA + 1e-10f) + 1e-10f);
        float pms   = pm * (1.f / TEMP);
        float mean3 = (t0 + t1 + t2) * (1.f / (3.f * TEMP));
        h = fmaxf(mean3 - pms + MRG, 0.f);
        if (t0 > -1e29f) {
            v = 1.f;
            m = fmaxf(t0 * (1.f / TEMP) - pms + MRG, 0.f);
        }
    }

    __shared__ float red[5][8];
    float vals[5] = {basic, h, m, hp, v};
    int lane = threadIdx.x & 31, warp = threadIdx.x >> 5;
    #pragma unroll
    for (int q = 0; q < 5; q++) {
        float x = vals[q];
        #pragma unroll
        for (int o = 16; o > 0; o >>= 1) x += __shfl_xor_sync(0xffffffffu, x, o);
        if (lane == 0) red[q][warp] = x;
    }
    __syncthreads();
    if (warp == 0 && lane == 0) {
        #pragma unroll
        for (int q = 0; q < 5; q++) {
            float x = 0.f;
            #pragma unroll
            for (int w = 0; w < 8; w++) x += red[q][w];
            g_blk[blockIdx.x * 5 + q] = x;
        }
    }
}

// ---------------------------------------------------------------------------
// Kernel 4: final scalar.
// ---------------------------------------------------------------------------
__global__ void kfin(float* __restrict__ out, int n) {
    int lane = threadIdx.x;   // 32 threads
    float acc[5];
    #pragma unroll
    for (int q = 0; q < 5; q++) {
        float x = 0.f;
        for (int i = lane; i < RED_BLOCKS; i += 32) x += g_blk[i * 5 + q];
        #pragma unroll
        for (int o = 16; o > 0; o >>= 1) x += __shfl_xor_sync(0xffffffffu, x, o);
        acc[q] = x;
    }
    float Bv = acc[0], Hv = acc[1], Mv = acc[2], HP = acc[3], V = acc[4];
    float n_hp = fmaxf(HP, 1.f);
    float n_v  = fmaxf(V, 1.f);
    float margin_loss = (V > 0.f) ? (Mv / n_v) : 0.f;
    float total = Bv / n_hp + 0.5f * (Hv / n_hp) + 0.1f * margin_loss;
    for (int i = lane; i < n; i += 32) out[i] = total;
}

// ---------------------------------------------------------------------------
extern "C" void kernel_launch(void* const* d_in, const int* in_sizes, int n_in,
                              void* d_out, int out_size) {
    const float* emb   = (const float*)d_in[0];
    const int*   lab32 = (const int*)d_in[1];
    (void)in_sizes; (void)n_in;

    cudaFuncSetAttribute(kmain, cudaFuncAttributeMaxDynamicSharedMemorySize, SMEM_TOTAL);

    klab<<<1, 256>>>(lab32);
    knorm<<<NB * 32 / 256, 256>>>(emb);
    kmain<<<NPAIR, NTHR, SMEM_TOTAL>>>();
    krow<<<RED_BLOCKS, 256>>>();
    kfin<<<1, 32>>>((float*)d_out, out_size);
}

// round 11
// speedup vs baseline: 1.5868x; 1.0673x over previous
#include <cuda_runtime.h>
#include <math.h>

// ---------------------------------------------------------------------------
// EnhancedContrastiveLoss — v11: v6 verbatim core (symmetric-half tf32
// mma.sync, 3-stage cp.async, staged two-round epilogue, 8-thread/row krow)
// + diag-last block ordering + klab folded into knorm as an extra CTA.
// ---------------------------------------------------------------------------

namespace {
constexpr int   NB   = 8192;
constexpr int   ND   = 256;
constexpr float TEMP = 0.07f;
constexpr float MRG  = 0.2f;
constexpr float NEGINF = -1e30f;
constexpr float CEXP = 20.609929059847869f;   // log2(e)/TEMP

constexpr int NBLK  = NB / 128;               // 64 row-blocks
constexpr int NOFF  = NBLK * (NBLK - 1) / 2;  // 2016 off-diagonal pairs
constexpr int NPAIR = NOFF + NBLK;            // 2080 CTAs
constexpr int NTHR  = 256;                    // 8 warps: 2(M) x 4(N)
constexpr int OST   = 36;                     // operand smem row stride (floats)
constexpr int DST   = 129;                    // D-tile smem row stride (floats)
constexpr int NSTAGE = 3;
constexpr int RED_BLOCKS = 256;

// dynamic smem layout (bytes)
constexpr int SM_OPA  = 0;                        // 3 x 18432 = 55296
constexpr int SM_OPB  = 55296;                    // 3 x 18432 = 55296
constexpr int SM_LABI = 110592;                   // 128 int
constexpr int SM_LABJ = 111104;                   // 128 int
constexpr int SMEM_TOTAL = 111616;
// post-GEMM overlays: D tile 128x129 f32 @0 (66048 B), staging @66560 (12288 B)
constexpr int SM_STG  = 66560;
}

__device__ float g_en[NB * ND];                // normalized, tf32-rounded
__device__ int   g_lab[NB];
__device__ float g_part[6 * NBLK * NB];        // [q][slot][row]
__device__ float g_blk[RED_BLOCKS * 5];

// ----------------------------- helpers ------------------------------------
__device__ __forceinline__ unsigned smem_u32(const void* p) {
    unsigned a;
    asm("{ .reg .u64 t; cvta.to.shared.u64 t, %1; cvt.u32.u64 %0, t; }" : "=r"(a) : "l"(p));
    return a;
}
__device__ __forceinline__ void cpasync16(unsigned dst, const void* src) {
    asm volatile("cp.async.cg.shared.global [%0], [%1], 16;" :: "r"(dst), "l"(src) : "memory");
}
#define CP_COMMIT() asm volatile("cp.async.commit_group;" ::: "memory")
#define CP_WAIT0()  asm volatile("cp.async.wait_group 0;"  ::: "memory")
#define CP_WAIT1()  asm volatile("cp.async.wait_group 1;"  ::: "memory")

__device__ __forceinline__ void mma_tf32(float c[4], const unsigned a[4], const unsigned b[2]) {
    asm volatile(
        "mma.sync.aligned.m16n8k8.row.col.f32.tf32.tf32.f32 "
        "{%0,%1,%2,%3}, {%4,%5,%6,%7}, {%8,%9}, {%0,%1,%2,%3};"
        : "+f"(c[0]), "+f"(c[1]), "+f"(c[2]), "+f"(c[3])
        : "r"(a[0]), "r"(a[1]), "r"(a[2]), "r"(a[3]), "r"(b[0]), "r"(b[1]));
}

__device__ __forceinline__ float ex2f(float x) {
    float y; asm("ex2.approx.f32 %0, %1;" : "=f"(y) : "f"(x)); return y;
}
__device__ __forceinline__ void ins3(float& t0, float& t1, float& t2, float x) {
    float m;
    m = fmaxf(t0, x); x = fminf(t0, x); t0 = m;
    m = fmaxf(t1, x); x = fminf(t1, x); t1 = m;
    t2 = fmaxf(t2, x);
}

// ---------------------------------------------------------------------------
// Kernel 1: L2 normalize + round-to-nearest-tf32. CTA 1024 instead runs the
// SAFE label dtype detection/normalization (byte-identical to v6's klab:
// reads only the first NB int32 words — in-bounds for both dtypes).
// ---------------------------------------------------------------------------
__global__ void knorm(const float* __restrict__ emb, const int* __restrict__ lab32) {
    if (blockIdx.x == NB * 32 / 256) {
        __shared__ int s_nz;
        if (threadIdx.x == 0) s_nz = 0;
        __syncthreads();
        int acc = 0;
        for (int i = threadIdx.x; i < NB / 2; i += blockDim.x) acc |= lab32[2 * i + 1];
        if (acc) atomicOr(&s_nz, 1);
        __syncthreads();
        const bool is64 = (s_nz == 0);
        for (int i = threadIdx.x; i < NB; i += blockDim.x)
            g_lab[i] = is64 ? lab32[2 * i] : lab32[i];
        return;
    }
    int gw   = (blockIdx.x * blockDim.x + threadIdx.x) >> 5;
    int lane = threadIdx.x & 31;
    if (gw >= NB) return;
    const float4* src = reinterpret_cast<const float4*>(emb + (size_t)gw * ND);
    float4 v0 = src[lane * 2];
    float4 v1 = src[lane * 2 + 1];
    float ss = v0.x*v0.x + v0.y*v0.y + v0.z*v0.z + v0.w*v0.w
             + v1.x*v1.x + v1.y*v1.y + v1.z*v1.z + v1.w*v1.w;
    #pragma unroll
    for (int o = 16; o > 0; o >>= 1) ss += __shfl_xor_sync(0xffffffffu, ss, o);
    float inv = 1.0f / fmaxf(sqrtf(ss), 1e-12f);
    float f[8] = {v0.x*inv, v0.y*inv, v0.z*inv, v0.w*inv,
                  v1.x*inv, v1.y*inv, v1.z*inv, v1.w*inv};
    #pragma unroll
    for (int i = 0; i < 8; i++) {
        unsigned b;
        asm("cvt.rna.tf32.f32 %0, %1;" : "=r"(b) : "f"(f[i]));
        f[i] = __uint_as_float(b);
    }
    float4* dst = reinterpret_cast<float4*>(g_en + (size_t)gw * ND);
    dst[lane * 2]     = make_float4(f[0], f[1], f[2], f[3]);
    dst[lane * 2 + 1] = make_float4(f[4], f[5], f[6], f[7]);
}

// ---------------------------------------------------------------------------
// Kernel 2: symmetric-half tf32 GEMM + two-view staged fused epilogue (v6),
// with diag-last block ordering (off-diagonals first, 64 diagonals last).
// Grid: 2080 CTAs. 256 threads. 3-stage pipeline, one __syncthreads/chunk.
// ---------------------------------------------------------------------------
__global__ void __launch_bounds__(NTHR, 2) kmain() {
    extern __shared__ char smem[];
    float* OpA  = (float*)(smem + SM_OPA);
    float* OpB  = (float*)(smem + SM_OPB);
    float* Ds   = (float*)smem;                 // overlays operands post-GEMM
    float* stg  = (float*)(smem + SM_STG);
    int*   labI = (int*)(smem + SM_LABI);
    int*   labJ = (int*)(smem + SM_LABJ);
    const unsigned sbA = smem_u32(OpA), sbB = smem_u32(OpB);

    const int tid   = threadIdx.x;
    const int lane  = tid & 31;
    const int wid   = tid >> 5;
    const int warpM = wid >> 2;          // 0..1
    const int warpN = wid & 3;           // 0..3
    const int qrow  = lane >> 2;         // 0..7
    const int qcol  = lane & 3;          // 0..3

    // block id -> (I, J): off-diagonals first (I < J), diagonals last
    int I, J;
    if (blockIdx.x < NOFF) {
        int i = 0, rem = blockIdx.x;
        while (rem >= NBLK - 1 - i) { rem -= NBLK - 1 - i; i++; }
        I = i; J = i + 1 + rem;
    } else {
        I = J = blockIdx.x - NOFF;
    }
    const int rowI = I * 128, rowJ = J * 128;
    const bool diag = (I == J);

    // labels into smem
    if (tid < 128) labI[tid] = g_lab[rowI + tid];
    else           labJ[tid - 128] = g_lab[rowJ + tid - 128];

    // chunk issue into stage g%3 (diag: A only, B aliases A)
    auto issue = [&](int g) {
        const int stage = g % NSTAGE;
        const int kc = g * 32;
        #pragma unroll
        for (int q = 0; q < 4; q++) {
            int idx = tid + q * NTHR;        // 0..1023
            int r = idx >> 3, f = (idx & 7) * 4;
            unsigned off = (unsigned)((stage * 128 + r) * OST + f) * 4u;
            cpasync16(sbA + off, g_en + (size_t)(rowI + r) * ND + kc + f);
            if (!diag)
                cpasync16(sbB + off, g_en + (size_t)(rowJ + r) * ND + kc + f);
        }
        CP_COMMIT();
    };

    float acc[4][4][4];
    #pragma unroll
    for (int i = 0; i < 4; i++)
        #pragma unroll
        for (int j = 0; j < 4; j++)
            #pragma unroll
            for (int c = 0; c < 4; c++) acc[i][j][c] = 0.f;

    issue(0); issue(1);

    for (int g = 0; g < 8; g++) {
        if (g < 7) CP_WAIT1();
        else       CP_WAIT0();
        __syncthreads();                     // all warps done with chunk g-1
        if (g + 2 < 8) issue(g + 2);

        const int stage = g % NSTAGE;
        const float* Apan = OpA + stage * 128 * OST;
        const float* Bpan = diag ? Apan : OpB + stage * 128 * OST;
        #pragma unroll
        for (int ks = 0; ks < 4; ks++) {
            const int kb = ks * 8;
            unsigned a[4][4], b[4][2];
            #pragma unroll
            for (int i = 0; i < 4; i++) {
                const float* ap = Apan + (size_t)(warpM * 64 + i * 16 + qrow) * OST + kb + qcol;
                a[i][0] = __float_as_uint(ap[0]);
                a[i][1] = __float_as_uint(ap[8 * OST]);
                a[i][2] = __float_as_uint(ap[4]);
                a[i][3] = __float_as_uint(ap[8 * OST + 4]);
            }
            #pragma unroll
            for (int j = 0; j < 4; j++) {
                const float* bp = Bpan + (size_t)(warpN * 32 + j * 8 + qrow) * OST + kb + qcol;
                b[j][0] = __float_as_uint(bp[0]);
                b[j][1] = __float_as_uint(bp[4]);
            }
            #pragma unroll
            for (int i = 0; i < 4; i++)
                #pragma unroll
                for (int j = 0; j < 4; j++)
                    mma_tf32(acc[i][j], a[i], b[j]);
        }
    }
    __syncthreads();                         // GEMM done; operand smem now dead

    // ---- stage D into smem (stride 129) ----
    #pragma unroll
    for (int i = 0; i < 4; i++) {
        #pragma unroll
        for (int j = 0; j < 4; j++) {
            const int rl0 = warpM * 64 + i * 16 + qrow;
            const int cl0 = warpN * 32 + j * 8 + 2 * qcol;
            Ds[(size_t)rl0 * DST + cl0]           = acc[i][j][0];
            Ds[(size_t)rl0 * DST + cl0 + 1]       = acc[i][j][1];
            Ds[(size_t)(rl0 + 8) * DST + cl0]     = acc[i][j][2];
            Ds[(size_t)(rl0 + 8) * DST + cl0 + 1] = acc[i][j][3];
        }
    }
    __syncthreads();

    // ---- task-parallel epilogue: 512 tasks = {view, half, idx} (v6 form) ----
    // view 0: rows of I scanning cols (slot J). view 1: cols (rows of J, slot I).
    // Diagonal blocks: only view 0 (256 tasks, one round).
    const int rounds = diag ? 1 : 2;
    for (int rr = 0; rr < rounds; rr++) {
        const int tau  = tid + rr * 256;
        const int view = tau >> 8;
        const int half = (tau >> 7) & 1;
        const int idx  = tau & 127;
        float sA = 0.f, sP = 0.f, pm = NEGINF;
        float t0 = NEGINF, t1 = NEGINF, t2 = NEGINF;
        if (view == 0) {
            const int lr = labI[idx];
            const float* dr = Ds + (size_t)idx * DST + half * 64;
            #pragma unroll 4
            for (int c = 0; c < 64; c++) {
                float d = dr[c];
                const int col = half * 64 + c;
                if (!(diag && col == idx)) {
                    float E = ex2f(d * CEXP);
                    sA += E;
                    if (lr == labJ[col]) { sP += E; pm = fmaxf(pm, d); }
                    else ins3(t0, t1, t2, d);
                }
            }
        } else {
            const int lc = labJ[idx];
            #pragma unroll 4
            for (int r = 0; r < 64; r++) {
                float d = Ds[(size_t)(half * 64 + r) * DST + idx];
                float E = ex2f(d * CEXP);
                if (lc == labI[half * 64 + r]) { sA += E; sP += E; pm = fmaxf(pm, d); }
                else { sA += E; ins3(t0, t1, t2, d); }
            }
        }
        float* p = stg + (size_t)tau * 6;
        p[0] = sA; p[1] = sP; p[2] = pm; p[3] = t0; p[4] = t1; p[5] = t2;
    }
    __syncthreads();

    // ---- merge halves and write g_part ----
    if (tid < 128 || !diag) {
        const int view = tid >> 7;
        const int idx  = tid & 127;
        const float* p0 = stg + (size_t)(view * 256 + idx) * 6;
        const float* p1 = p0 + 128 * 6;
        float sA = p0[0] + p1[0];
        float sP = p0[1] + p1[1];
        float pm = fmaxf(p0[2], p1[2]);
        float t0 = p0[3], t1 = p0[4], t2 = p0[5];
        ins3(t0, t1, t2, p1[3]); ins3(t0, t1, t2, p1[4]); ins3(t0, t1, t2, p1[5]);
        const int slot = view ? I : J;
        const int grow = (view ? rowJ : rowI) + idx;
        g_part[(size_t)(0 * NBLK + slot) * NB + grow] = sA;
        g_part[(size_t)(1 * NBLK + slot) * NB + grow] = sP;
        g_part[(size_t)(2 * NBLK + slot) * NB + grow] = pm;
        g_part[(size_t)(3 * NBLK + slot) * NB + grow] = t0;
        g_part[(size_t)(4 * NBLK + slot) * NB + grow] = t1;
        g_part[(size_t)(5 * NBLK + slot) * NB + grow] = t2;
    }
}

// ---------------------------------------------------------------------------
// Kernel 3: per-row merge of 64 slot partials (8 threads/row) + loss terms.
// Grid 256 x 256: gid>>3 = row, gid&7 = slot slice of 8.   (v6-proven)
// ---------------------------------------------------------------------------
__global__ void krow() {
    const int gid = blockIdx.x * blockDim.x + threadIdx.x;
    const int row = gid >> 3;
    const int sl  = (gid & 7) * 8;
    float sA = 0.f, sP = 0.f, pm = NEGINF;
    float t0 = NEGINF, t1 = NEGINF, t2 = NEGINF;
    #pragma unroll
    for (int s = 0; s < 8; s++) {
        const int slot = sl + s;
        sA += g_part[(size_t)(0 * NBLK + slot) * NB + row];
        sP += g_part[(size_t)(1 * NBLK + slot) * NB + row];
        pm  = fmaxf(pm, g_part[(size_t)(2 * NBLK + slot) * NB + row]);
        ins3(t0, t1, t2, g_part[(size_t)(3 * NBLK + slot) * NB + row]);
        ins3(t0, t1, t2, g_part[(size_t)(4 * NBLK + slot) * NB + row]);
        ins3(t0, t1, t2, g_part[(size_t)(5 * NBLK + slot) * NB + row]);
    }
    #pragma unroll
    for (int o = 1; o <= 4; o <<= 1) {
        sA += __shfl_xor_sync(0xffffffffu, sA, o);
        sP += __shfl_xor_sync(0xffffffffu, sP, o);
        pm  = fmaxf(pm, __shfl_xor_sync(0xffffffffu, pm, o));
        float o0 = __shfl_xor_sync(0xffffffffu, t0, o);
        float o1 = __shfl_xor_sync(0xffffffffu, t1, o);
        float o2 = __shfl_xor_sync(0xffffffffu, t2, o);
        ins3(t0, t1, t2, o0); ins3(t0, t1, t2, o1); ins3(t0, t1, t2, o2);
    }

    float basic = 0.f, h = 0.f, m = 0.f, hp = 0.f, v = 0.f;
    if ((threadIdx.x & 7) == 0 && pm > -1e29f) {
        hp = 1.f;
        basic = -logf(sP / (sA + 1e-10f) + 1e-10f);
        float pms   = pm * (1.f / TEMP);
        float mean3 = (t0 + t1 + t2) * (1.f / (3.f * TEMP));
        h = fmaxf(mean3 - pms + MRG, 0.f);
        if (t0 > -1e29f) {
            v = 1.f;
            m = fmaxf(t0 * (1.f / TEMP) - pms + MRG, 0.f);
        }
    }

    __shared__ float red[5][8];
    float vals[5] = {basic, h, m, hp, v};
    int lane = threadIdx.x & 31, warp = threadIdx.x >> 5;
    #pragma unroll
    for (int q = 0; q < 5; q++) {
        float x = vals[q];
        #pragma unroll
        for (int o = 16; o > 0; o >>= 1) x += __shfl_xor_sync(0xffffffffu, x, o);
        if (lane == 0) red[q][warp] = x;
    }
    __syncthreads();
    if (warp == 0 && lane == 0) {
        #pragma unroll
        for (int q = 0; q < 5; q++) {
            float x = 0.f;
            #pragma unroll
            for (int w = 0; w < 8; w++) x += red[q][w];
            g_blk[blockIdx.x * 5 + q] = x;
        }
    }
}

// ---------------------------------------------------------------------------
// Kernel 4: final scalar.
// ---------------------------------------------------------------------------
__global__ void kfin(float* __restrict__ out, int n) {
    int lane = threadIdx.x;   // 32 threads
    float acc[5];
    #pragma unroll
    for (int q = 0; q < 5; q++) {
        float x = 0.f;
        for (int i = lane; i < RED_BLOCKS; i += 32) x += g_blk[i * 5 + q];
        #pragma unroll
        for (int o = 16; o > 0; o >>= 1) x += __shfl_xor_sync(0xffffffffu, x, o);
        acc[q] = x;
    }
    float Bv = acc[0], Hv = acc[1], Mv = acc[2], HP = acc[3], V = acc[4];
    float n_hp = fmaxf(HP, 1.f);
    float n_v  = fmaxf(V, 1.f);
    float margin_loss = (V > 0.f) ? (Mv / n_v) : 0.f;
    float total = Bv / n_hp + 0.5f * (Hv / n_hp) + 0.1f * margin_loss;
    for (int i = lane; i < n; i += 32) out[i] = total;
}

// ---------------------------------------------------------------------------
extern "C" void kernel_launch(void* const* d_in, const int* in_sizes, int n_in,
                              void* d_out, int out_size) {
    const float* emb   = (const float*)d_in[0];
    const int*   lab32 = (const int*)d_in[1];
    (void)in_sizes; (void)n_in;

    cudaFuncSetAttribute(kmain, cudaFuncAttributeMaxDynamicSharedMemorySize, SMEM_TOTAL);

    knorm<<<NB * 32 / 256 + 1, 256>>>(emb, lab32);   // +1 CTA runs label detect
    kmain<<<NPAIR, NTHR, SMEM_TOTAL>>>();
    krow<<<RED_BLOCKS, 256>>>();
    kfin<<<1, 32>>>((float*)d_out, out_size);
}

// round 12
// speedup vs baseline: 1.6051x; 1.0115x over previous
#include <cuda_runtime.h>
#include <math.h>

// ---------------------------------------------------------------------------
// EnhancedContrastiveLoss — v12: v11 verbatim core (symmetric-half tf32
// mma.sync, 3-stage cp.async, staged two-round epilogue, diag-last ordering,
// klab folded into knorm) + kfin fused into krow via last-block reduction
// (removes one kernel launch, measured 9.4 us).
// ---------------------------------------------------------------------------

namespace {
constexpr int   NB   = 8192;
constexpr int   ND   = 256;
constexpr float TEMP = 0.07f;
constexpr float MRG  = 0.2f;
constexpr float NEGINF = -1e30f;
constexpr float CEXP = 20.609929059847869f;   // log2(e)/TEMP

constexpr int NBLK  = NB / 128;               // 64 row-blocks
constexpr int NOFF  = NBLK * (NBLK - 1) / 2;  // 2016 off-diagonal pairs
constexpr int NPAIR = NOFF + NBLK;            // 2080 CTAs
constexpr int NTHR  = 256;                    // 8 warps: 2(M) x 4(N)
constexpr int OST   = 36;                     // operand smem row stride (floats)
constexpr int DST   = 129;                    // D-tile smem row stride (floats)
constexpr int NSTAGE = 3;
constexpr int RED_BLOCKS = 256;

// dynamic smem layout (bytes)
constexpr int SM_OPA  = 0;                        // 3 x 18432 = 55296
constexpr int SM_OPB  = 55296;                    // 3 x 18432 = 55296
constexpr int SM_LABI = 110592;                   // 128 int
constexpr int SM_LABJ = 111104;                   // 128 int
constexpr int SMEM_TOTAL = 111616;
// post-GEMM overlays: D tile 128x129 f32 @0 (66048 B), staging @66560 (12288 B)
constexpr int SM_STG  = 66560;
}

__device__ float g_en[NB * ND];                // normalized, tf32-rounded
__device__ int   g_lab[NB];
__device__ float g_part[6 * NBLK * NB];        // [q][slot][row]
__device__ float g_blk[RED_BLOCKS * 5];
__device__ unsigned g_ctr;                     // last-block counter (reset each call)

// ----------------------------- helpers ------------------------------------
__device__ __forceinline__ unsigned smem_u32(const void* p) {
    unsigned a;
    asm("{ .reg .u64 t; cvta.to.shared.u64 t, %1; cvt.u32.u64 %0, t; }" : "=r"(a) : "l"(p));
    return a;
}
__device__ __forceinline__ void cpasync16(unsigned dst, const void* src) {
    asm volatile("cp.async.cg.shared.global [%0], [%1], 16;" :: "r"(dst), "l"(src) : "memory");
}
#define CP_COMMIT() asm volatile("cp.async.commit_group;" ::: "memory")
#define CP_WAIT0()  asm volatile("cp.async.wait_group 0;"  ::: "memory")
#define CP_WAIT1()  asm volatile("cp.async.wait_group 1;"  ::: "memory")

__device__ __forceinline__ void mma_tf32(float c[4], const unsigned a[4], const unsigned b[2]) {
    asm volatile(
        "mma.sync.aligned.m16n8k8.row.col.f32.tf32.tf32.f32 "
        "{%0,%1,%2,%3}, {%4,%5,%6,%7}, {%8,%9}, {%0,%1,%2,%3};"
        : "+f"(c[0]), "+f"(c[1]), "+f"(c[2]), "+f"(c[3])
        : "r"(a[0]), "r"(a[1]), "r"(a[2]), "r"(a[3]), "r"(b[0]), "r"(b[1]));
}

__device__ __forceinline__ float ex2f(float x) {
    float y; asm("ex2.approx.f32 %0, %1;" : "=f"(y) : "f"(x)); return y;
}
__device__ __forceinline__ void ins3(float& t0, float& t1, float& t2, float x) {
    float m;
    m = fmaxf(t0, x); x = fminf(t0, x); t0 = m;
    m = fmaxf(t1, x); x = fminf(t1, x); t1 = m;
    t2 = fmaxf(t2, x);
}

// ---------------------------------------------------------------------------
// Kernel 1: L2 normalize + round-to-nearest-tf32. CTA 1024 instead runs the
// SAFE label dtype detection (reads only first NB int32 words — in-bounds for
// both dtypes) and resets the last-block counter for this call.
// ---------------------------------------------------------------------------
__global__ void knorm(const float* __restrict__ emb, const int* __restrict__ lab32) {
    if (blockIdx.x == NB * 32 / 256) {
        __shared__ int s_nz;
        if (threadIdx.x == 0) { s_nz = 0; g_ctr = 0u; }
        __syncthreads();
        int acc = 0;
        for (int i = threadIdx.x; i < NB / 2; i += blockDim.x) acc |= lab32[2 * i + 1];
        if (acc) atomicOr(&s_nz, 1);
        __syncthreads();
        const bool is64 = (s_nz == 0);
        for (int i = threadIdx.x; i < NB; i += blockDim.x)
            g_lab[i] = is64 ? lab32[2 * i] : lab32[i];
        return;
    }
    int gw   = (blockIdx.x * blockDim.x + threadIdx.x) >> 5;
    int lane = threadIdx.x & 31;
    if (gw >= NB) return;
    const float4* src = reinterpret_cast<const float4*>(emb + (size_t)gw * ND);
    float4 v0 = src[lane * 2];
    float4 v1 = src[lane * 2 + 1];
    float ss = v0.x*v0.x + v0.y*v0.y + v0.z*v0.z + v0.w*v0.w
             + v1.x*v1.x + v1.y*v1.y + v1.z*v1.z + v1.w*v1.w;
    #pragma unroll
    for (int o = 16; o > 0; o >>= 1) ss += __shfl_xor_sync(0xffffffffu, ss, o);
    float inv = 1.0f / fmaxf(sqrtf(ss), 1e-12f);
    float f[8] = {v0.x*inv, v0.y*inv, v0.z*inv, v0.w*inv,
                  v1.x*inv, v1.y*inv, v1.z*inv, v1.w*inv};
    #pragma unroll
    for (int i = 0; i < 8; i++) {
        unsigned b;
        asm("cvt.rna.tf32.f32 %0, %1;" : "=r"(b) : "f"(f[i]));
        f[i] = __uint_as_float(b);
    }
    float4* dst = reinterpret_cast<float4*>(g_en + (size_t)gw * ND);
    dst[lane * 2]     = make_float4(f[0], f[1], f[2], f[3]);
    dst[lane * 2 + 1] = make_float4(f[4], f[5], f[6], f[7]);
}

// ---------------------------------------------------------------------------
// Kernel 2: symmetric-half tf32 GEMM + two-view staged fused epilogue,
// diag-last block ordering. (byte-identical to v11)
// ---------------------------------------------------------------------------
__global__ void __launch_bounds__(NTHR, 2) kmain() {
    extern __shared__ char smem[];
    float* OpA  = (float*)(smem + SM_OPA);
    float* OpB  = (float*)(smem + SM_OPB);
    float* Ds   = (float*)smem;                 // overlays operands post-GEMM
    float* stg  = (float*)(smem + SM_STG);
    int*   labI = (int*)(smem + SM_LABI);
    int*   labJ = (int*)(smem + SM_LABJ);
    const unsigned sbA = smem_u32(OpA), sbB = smem_u32(OpB);

    const int tid   = threadIdx.x;
    const int lane  = tid & 31;
    const int wid   = tid >> 5;
    const int warpM = wid >> 2;          // 0..1
    const int warpN = wid & 3;           // 0..3
    const int qrow  = lane >> 2;         // 0..7
    const int qcol  = lane & 3;          // 0..3

    // block id -> (I, J): off-diagonals first (I < J), diagonals last
    int I, J;
    if (blockIdx.x < NOFF) {
        int i = 0, rem = blockIdx.x;
        while (rem >= NBLK - 1 - i) { rem -= NBLK - 1 - i; i++; }
        I = i; J = i + 1 + rem;
    } else {
        I = J = blockIdx.x - NOFF;
    }
    const int rowI = I * 128, rowJ = J * 128;
    const bool diag = (I == J);

    // labels into smem
    if (tid < 128) labI[tid] = g_lab[rowI + tid];
    else           labJ[tid - 128] = g_lab[rowJ + tid - 128];

    // chunk issue into stage g%3 (diag: A only, B aliases A)
    auto issue = [&](int g) {
        const int stage = g % NSTAGE;
        const int kc = g * 32;
        #pragma unroll
        for (int q = 0; q < 4; q++) {
            int idx = tid + q * NTHR;        // 0..1023
            int r = idx >> 3, f = (idx & 7) * 4;
            unsigned off = (unsigned)((stage * 128 + r) * OST + f) * 4u;
            cpasync16(sbA + off, g_en + (size_t)(rowI + r) * ND + kc + f);
            if (!diag)
                cpasync16(sbB + off, g_en + (size_t)(rowJ + r) * ND + kc + f);
        }
        CP_COMMIT();
    };

    float acc[4][4][4];
    #pragma unroll
    for (int i = 0; i < 4; i++)
        #pragma unroll
        for (int j = 0; j < 4; j++)
            #pragma unroll
            for (int c = 0; c < 4; c++) acc[i][j][c] = 0.f;

    issue(0); issue(1);

    for (int g = 0; g < 8; g++) {
        if (g < 7) CP_WAIT1();
        else       CP_WAIT0();
        __syncthreads();                     // all warps done with chunk g-1
        if (g + 2 < 8) issue(g + 2);

        const int stage = g % NSTAGE;
        const float* Apan = OpA + stage * 128 * OST;
        const float* Bpan = diag ? Apan : OpB + stage * 128 * OST;
        #pragma unroll
        for (int ks = 0; ks < 4; ks++) {
            const int kb = ks * 8;
            unsigned a[4][4], b[4][2];
            #pragma unroll
            for (int i = 0; i < 4; i++) {
                const float* ap = Apan + (size_t)(warpM * 64 + i * 16 + qrow) * OST + kb + qcol;
                a[i][0] = __float_as_uint(ap[0]);
                a[i][1] = __float_as_uint(ap[8 * OST]);
                a[i][2] = __float_as_uint(ap[4]);
                a[i][3] = __float_as_uint(ap[8 * OST + 4]);
            }
            #pragma unroll
            for (int j = 0; j < 4; j++) {
                const float* bp = Bpan + (size_t)(warpN * 32 + j * 8 + qrow) * OST + kb + qcol;
                b[j][0] = __float_as_uint(bp[0]);
                b[j][1] = __float_as_uint(bp[4]);
            }
            #pragma unroll
            for (int i = 0; i < 4; i++)
                #pragma unroll
                for (int j = 0; j < 4; j++)
                    mma_tf32(acc[i][j], a[i], b[j]);
        }
    }
    __syncthreads();                         // GEMM done; operand smem now dead

    // ---- stage D into smem (stride 129) ----
    #pragma unroll
    for (int i = 0; i < 4; i++) {
        #pragma unroll
        for (int j = 0; j < 4; j++) {
            const int rl0 = warpM * 64 + i * 16 + qrow;
            const int cl0 = warpN * 32 + j * 8 + 2 * qcol;
            Ds[(size_t)rl0 * DST + cl0]           = acc[i][j][0];
            Ds[(size_t)rl0 * DST + cl0 + 1]       = acc[i][j][1];
            Ds[(size_t)(rl0 + 8) * DST + cl0]     = acc[i][j][2];
            Ds[(size_t)(rl0 + 8) * DST + cl0 + 1] = acc[i][j][3];
        }
    }
    __syncthreads();

    // ---- task-parallel epilogue: 512 tasks = {view, half, idx} ----
    const int rounds = diag ? 1 : 2;
    for (int rr = 0; rr < rounds; rr++) {
        const int tau  = tid + rr * 256;
        const int view = tau >> 8;
        const int half = (tau >> 7) & 1;
        const int idx  = tau & 127;
        float sA = 0.f, sP = 0.f, pm = NEGINF;
        float t0 = NEGINF, t1 = NEGINF, t2 = NEGINF;
        if (view == 0) {
            const int lr = labI[idx];
            const float* dr = Ds + (size_t)idx * DST + half * 64;
            #pragma unroll 4
            for (int c = 0; c < 64; c++) {
                float d = dr[c];
                const int col = half * 64 + c;
                if (!(diag && col == idx)) {
                    float E = ex2f(d * CEXP);
                    sA += E;
                    if (lr == labJ[col]) { sP += E; pm = fmaxf(pm, d); }
                    else ins3(t0, t1, t2, d);
                }
            }
        } else {
            const int lc = labJ[idx];
            #pragma unroll 4
            for (int r = 0; r < 64; r++) {
                float d = Ds[(size_t)(half * 64 + r) * DST + idx];
                float E = ex2f(d * CEXP);
                if (lc == labI[half * 64 + r]) { sA += E; sP += E; pm = fmaxf(pm, d); }
                else { sA += E; ins3(t0, t1, t2, d); }
            }
        }
        float* p = stg + (size_t)tau * 6;
        p[0] = sA; p[1] = sP; p[2] = pm; p[3] = t0; p[4] = t1; p[5] = t2;
    }
    __syncthreads();

    // ---- merge halves and write g_part ----
    if (tid < 128 || !diag) {
        const int view = tid >> 7;
        const int idx  = tid & 127;
        const float* p0 = stg + (size_t)(view * 256 + idx) * 6;
        const float* p1 = p0 + 128 * 6;
        float sA = p0[0] + p1[0];
        float sP = p0[1] + p1[1];
        float pm = fmaxf(p0[2], p1[2]);
        float t0 = p0[3], t1 = p0[4], t2 = p0[5];
        ins3(t0, t1, t2, p1[3]); ins3(t0, t1, t2, p1[4]); ins3(t0, t1, t2, p1[5]);
        const int slot = view ? I : J;
        const int grow = (view ? rowJ : rowI) + idx;
        g_part[(size_t)(0 * NBLK + slot) * NB + grow] = sA;
        g_part[(size_t)(1 * NBLK + slot) * NB + grow] = sP;
        g_part[(size_t)(2 * NBLK + slot) * NB + grow] = pm;
        g_part[(size_t)(3 * NBLK + slot) * NB + grow] = t0;
        g_part[(size_t)(4 * NBLK + slot) * NB + grow] = t1;
        g_part[(size_t)(5 * NBLK + slot) * NB + grow] = t2;
    }
}

// ---------------------------------------------------------------------------
// Kernel 3: per-row merge of 64 slot partials (8 threads/row) + loss terms,
// block-reduce to g_blk, then the LAST block performs the final scalar
// reduction and writes d_out (fused former kfin).
// ---------------------------------------------------------------------------
__global__ void krow(float* __restrict__ out, int n) {
    const int gid = blockIdx.x * blockDim.x + threadIdx.x;
    const int row = gid >> 3;
    const int sl  = (gid & 7) * 8;
    float sA = 0.f, sP = 0.f, pm = NEGINF;
    float t0 = NEGINF, t1 = NEGINF, t2 = NEGINF;
    #pragma unroll
    for (int s = 0; s < 8; s++) {
        const int slot = sl + s;
        sA += g_part[(size_t)(0 * NBLK + slot) * NB + row];
        sP += g_part[(size_t)(1 * NBLK + slot) * NB + row];
        pm  = fmaxf(pm, g_part[(size_t)(2 * NBLK + slot) * NB + row]);
        ins3(t0, t1, t2, g_part[(size_t)(3 * NBLK + slot) * NB + row]);
        ins3(t0, t1, t2, g_part[(size_t)(4 * NBLK + slot) * NB + row]);
        ins3(t0, t1, t2, g_part[(size_t)(5 * NBLK + slot) * NB + row]);
    }
    #pragma unroll
    for (int o = 1; o <= 4; o <<= 1) {
        sA += __shfl_xor_sync(0xffffffffu, sA, o);
        sP += __shfl_xor_sync(0xffffffffu, sP, o);
        pm  = fmaxf(pm, __shfl_xor_sync(0xffffffffu, pm, o));
        float o0 = __shfl_xor_sync(0xffffffffu, t0, o);
        float o1 = __shfl_xor_sync(0xffffffffu, t1, o);
        float o2 = __shfl_xor_sync(0xffffffffu, t2, o);
        ins3(t0, t1, t2, o0); ins3(t0, t1, t2, o1); ins3(t0, t1, t2, o2);
    }

    float basic = 0.f, h = 0.f, m = 0.f, hp = 0.f, v = 0.f;
    if ((threadIdx.x & 7) == 0 && pm > -1e29f) {
        hp = 1.f;
        basic = -logf(sP / (sA + 1e-10f) + 1e-10f);
        float pms   = pm * (1.f / TEMP);
        float mean3 = (t0 + t1 + t2) * (1.f / (3.f * TEMP));
        h = fmaxf(mean3 - pms + MRG, 0.f);
        if (t0 > -1e29f) {
            v = 1.f;
            m = fmaxf(t0 * (1.f / TEMP) - pms + MRG, 0.f);
        }
    }

    __shared__ float red[5][8];
    float vals[5] = {basic, h, m, hp, v};
    int lane = threadIdx.x & 31, warp = threadIdx.x >> 5;
    #pragma unroll
    for (int q = 0; q < 5; q++) {
        float x = vals[q];
        #pragma unroll
        for (int o = 16; o > 0; o >>= 1) x += __shfl_xor_sync(0xffffffffu, x, o);
        if (lane == 0) red[q][warp] = x;
    }
    __syncthreads();
    if (warp == 0 && lane == 0) {
        #pragma unroll
        for (int q = 0; q < 5; q++) {
            float x = 0.f;
            #pragma unroll
            for (int w = 0; w < 8; w++) x += red[q][w];
            g_blk[blockIdx.x * 5 + q] = x;
        }
    }

    // ---- last-block final reduction (fused kfin) ----
    __shared__ bool s_last;
    if (threadIdx.x == 0) {
        __threadfence();                       // g_blk visible before count
        unsigned t = atomicAdd(&g_ctr, 1u);
        s_last = (t == (unsigned)(RED_BLOCKS - 1));
    }
    __syncthreads();
    if (!s_last) return;
    __threadfence();                           // see all g_blk writes

    // 256 threads: thread b holds block-b partials; reduce across block.
    float acc[5];
    #pragma unroll
    for (int q = 0; q < 5; q++) acc[q] = g_blk[threadIdx.x * 5 + q];
    __shared__ float fred[5][8];
    #pragma unroll
    for (int q = 0; q < 5; q++) {
        float x = acc[q];
        #pragma unroll
        for (int o = 16; o > 0; o >>= 1) x += __shfl_xor_sync(0xffffffffu, x, o);
        if (lane == 0) fred[q][warp] = x;
    }
    __syncthreads();
    if (threadIdx.x == 0) {
        float tot[5];
        #pragma unroll
        for (int q = 0; q < 5; q++) {
            float x = 0.f;
            #pragma unroll
            for (int w = 0; w < 8; w++) x += fred[q][w];
            tot[q] = x;
        }
        float n_hp = fmaxf(tot[3], 1.f);
        float n_v  = fmaxf(tot[4], 1.f);
        float margin_loss = (tot[4] > 0.f) ? (tot[2] / n_v) : 0.f;
        float total = tot[0] / n_hp + 0.5f * (tot[1] / n_hp) + 0.1f * margin_loss;
        for (int i = 0; i < n; i++) out[i] = total;
    }
}

// ---------------------------------------------------------------------------
extern "C" void kernel_launch(void* const* d_in, const int* in_sizes, int n_in,
                              void* d_out, int out_size) {
    const float* emb   = (const float*)d_in[0];
    const int*   lab32 = (const int*)d_in[1];
    (void)in_sizes; (void)n_in;

    cudaFuncSetAttribute(kmain, cudaFuncAttributeMaxDynamicSharedMemorySize, SMEM_TOTAL);

    knorm<<<NB * 32 / 256 + 1, 256>>>(emb, lab32);   // +1 CTA: label detect + ctr reset
    kmain<<<NPAIR, NTHR, SMEM_TOTAL>>>();
    krow<<<RED_BLOCKS, 256>>>((float*)d_out, out_size);
}

// round 13
// speedup vs baseline: 1.7457x; 1.0876x over previous
#include <cuda_runtime.h>
#include <math.h>

// ---------------------------------------------------------------------------
// EnhancedContrastiveLoss — v13: v12 + paired-fragment column permutation.
// g_en columns permuted within each 8-group to [0,4,1,5,2,6,3,7] so each
// m16n8k8 tf32 fragment pair (k+q, k+q+4) is one LDS.64. Operand smem uses
// stride-32 rows with XOR swizzle (pos ^ (row&3)*8) — conflict-free LDS.64.
// Halves GEMM-loop LDS issue count (96 -> 48 per chunk): issue-bound -> tensor-bound.
// ---------------------------------------------------------------------------

namespace {
constexpr int   NB   = 8192;
constexpr int   ND   = 256;
constexpr float TEMP = 0.07f;
constexpr float MRG  = 0.2f;
constexpr float NEGINF = -1e30f;
constexpr float CEXP = 20.609929059847869f;   // log2(e)/TEMP

constexpr int NBLK  = NB / 128;               // 64 row-blocks
constexpr int NOFF  = NBLK * (NBLK - 1) / 2;  // 2016 off-diagonal pairs
constexpr int NPAIR = NOFF + NBLK;            // 2080 CTAs
constexpr int NTHR  = 256;                    // 8 warps: 2(M) x 4(N)
constexpr int DST   = 129;                    // D-tile smem row stride (floats)
constexpr int NSTAGE = 3;
constexpr int RED_BLOCKS = 256;

// dynamic smem layout (bytes). Operand rows: 32 floats, XOR-swizzled.
constexpr int SM_OPA  = 0;                        // 3 x 16384 = 49152
constexpr int SM_OPB  = 49152;                    // 3 x 16384 = 49152
constexpr int SM_LABI = 98304;                    // 128 int
constexpr int SM_LABJ = 98816;                    // 128 int
constexpr int SMEM_TOTAL = 99328;
// post-GEMM overlays: D tile 128x129 f32 @0 (66048 B), staging @66560 (12288 B)
constexpr int SM_STG  = 66560;
}

__device__ float g_en[NB * ND];                // normalized, tf32-rounded, PAIR-PERMUTED
__device__ int   g_lab[NB];
__device__ float g_part[6 * NBLK * NB];        // [q][slot][row]
__device__ float g_blk[RED_BLOCKS * 5];
__device__ unsigned g_ctr;                     // last-block counter (reset each call)

// ----------------------------- helpers ------------------------------------
__device__ __forceinline__ unsigned smem_u32(const void* p) {
    unsigned a;
    asm("{ .reg .u64 t; cvta.to.shared.u64 t, %1; cvt.u32.u64 %0, t; }" : "=r"(a) : "l"(p));
    return a;
}
__device__ __forceinline__ void cpasync16(unsigned dst, const void* src) {
    asm volatile("cp.async.cg.shared.global [%0], [%1], 16;" :: "r"(dst), "l"(src) : "memory");
}
#define CP_COMMIT() asm volatile("cp.async.commit_group;" ::: "memory")
#define CP_WAIT0()  asm volatile("cp.async.wait_group 0;"  ::: "memory")
#define CP_WAIT1()  asm volatile("cp.async.wait_group 1;"  ::: "memory")

__device__ __forceinline__ void mma_tf32(float c[4], const unsigned a[4], const unsigned b[2]) {
    asm volatile(
        "mma.sync.aligned.m16n8k8.row.col.f32.tf32.tf32.f32 "
        "{%0,%1,%2,%3}, {%4,%5,%6,%7}, {%8,%9}, {%0,%1,%2,%3};"
        : "+f"(c[0]), "+f"(c[1]), "+f"(c[2]), "+f"(c[3])
        : "r"(a[0]), "r"(a[1]), "r"(a[2]), "r"(a[3]), "r"(b[0]), "r"(b[1]));
}

__device__ __forceinline__ float ex2f(float x) {
    float y; asm("ex2.approx.f32 %0, %1;" : "=f"(y) : "f"(x)); return y;
}
__device__ __forceinline__ void ins3(float& t0, float& t1, float& t2, float x) {
    float m;
    m = fmaxf(t0, x); x = fminf(t0, x); t0 = m;
    m = fmaxf(t1, x); x = fminf(t1, x); t1 = m;
    t2 = fmaxf(t2, x);
}

// ---------------------------------------------------------------------------
// Kernel 1: L2 normalize + tf32 round + pair-permuted store.
// Each lane owns one aligned 8-column group; stores in order [0,4,1,5,2,6,3,7].
// CTA 1024 runs the SAFE label dtype detection + counter reset (v12-proven).
// ---------------------------------------------------------------------------
__global__ void knorm(const float* __restrict__ emb, const int* __restrict__ lab32) {
    if (blockIdx.x == NB * 32 / 256) {
        __shared__ int s_nz;
        if (threadIdx.x == 0) { s_nz = 0; g_ctr = 0u; }
        __syncthreads();
        int acc = 0;
        for (int i = threadIdx.x; i < NB / 2; i += blockDim.x) acc |= lab32[2 * i + 1];
        if (acc) atomicOr(&s_nz, 1);
        __syncthreads();
        const bool is64 = (s_nz == 0);
        for (int i = threadIdx.x; i < NB; i += blockDim.x)
            g_lab[i] = is64 ? lab32[2 * i] : lab32[i];
        return;
    }
    int gw   = (blockIdx.x * blockDim.x + threadIdx.x) >> 5;
    int lane = threadIdx.x & 31;
    if (gw >= NB) return;
    const float4* src = reinterpret_cast<const float4*>(emb + (size_t)gw * ND);
    float4 v0 = src[lane * 2];
    float4 v1 = src[lane * 2 + 1];
    float ss = v0.x*v0.x + v0.y*v0.y + v0.z*v0.z + v0.w*v0.w
             + v1.x*v1.x + v1.y*v1.y + v1.z*v1.z + v1.w*v1.w;
    #pragma unroll
    for (int o = 16; o > 0; o >>= 1) ss += __shfl_xor_sync(0xffffffffu, ss, o);
    float inv = 1.0f / fmaxf(sqrtf(ss), 1e-12f);
    float f[8] = {v0.x*inv, v0.y*inv, v0.z*inv, v0.w*inv,
                  v1.x*inv, v1.y*inv, v1.z*inv, v1.w*inv};
    #pragma unroll
    for (int i = 0; i < 8; i++) {
        unsigned b;
        asm("cvt.rna.tf32.f32 %0, %1;" : "=r"(b) : "f"(f[i]));
        f[i] = __uint_as_float(b);
    }
    // pair-permuted store: positions 0..7 <- cols [0,4,1,5,2,6,3,7]
    float4* dst = reinterpret_cast<float4*>(g_en + (size_t)gw * ND);
    dst[lane * 2]     = make_float4(f[0], f[4], f[1], f[5]);
    dst[lane * 2 + 1] = make_float4(f[2], f[6], f[3], f[7]);
}

// ---------------------------------------------------------------------------
// Kernel 2: symmetric-half tf32 GEMM (LDS.64 fragment loads) + two-view
// staged fused epilogue, diag-last block ordering.
// ---------------------------------------------------------------------------
__global__ void __launch_bounds__(NTHR, 2) kmain() {
    extern __shared__ char smem[];
    float* OpA  = (float*)(smem + SM_OPA);
    float* OpB  = (float*)(smem + SM_OPB);
    float* Ds   = (float*)smem;                 // overlays operands post-GEMM
    float* stg  = (float*)(smem + SM_STG);
    int*   labI = (int*)(smem + SM_LABI);
    int*   labJ = (int*)(smem + SM_LABJ);
    const unsigned sbA = smem_u32(OpA), sbB = smem_u32(OpB);

    const int tid   = threadIdx.x;
    const int lane  = tid & 31;
    const int wid   = tid >> 5;
    const int warpM = wid >> 2;          // 0..1
    const int warpN = wid & 3;           // 0..3
    const int qrow  = lane >> 2;         // 0..7
    const int qcol  = lane & 3;          // 0..3
    const int rsw   = (qrow & 3) * 8;    // row-XOR swizzle term (rows stride 8 share it)

    // block id -> (I, J): off-diagonals first (I < J), diagonals last
    int I, J;
    if (blockIdx.x < NOFF) {
        int i = 0, rem = blockIdx.x;
        while (rem >= NBLK - 1 - i) { rem -= NBLK - 1 - i; i++; }
        I = i; J = i + 1 + rem;
    } else {
        I = J = blockIdx.x - NOFF;
    }
    const int rowI = I * 128, rowJ = J * 128;
    const bool diag = (I == J);

    // labels into smem
    if (tid < 128) labI[tid] = g_lab[rowI + tid];
    else           labJ[tid - 128] = g_lab[rowJ + tid - 128];

    // chunk issue into stage g%3 (diag: A only, B aliases A).
    // dst position within row: (f*4) ^ ((r&3)*8)  — XOR swizzle, 16B groups intact.
    auto issue = [&](int g) {
        const int stage = g % NSTAGE;
        const int kc = g * 32;
        #pragma unroll
        for (int q = 0; q < 4; q++) {
            int idx = tid + q * NTHR;        // 0..1023
            int r = idx >> 3, f = idx & 7;
            int pos = (f * 4) ^ ((r & 3) * 8);
            unsigned off = (unsigned)((stage * 128 + r) * 32 + pos) * 4u;
            cpasync16(sbA + off, g_en + (size_t)(rowI + r) * ND + kc + f * 4);
            if (!diag)
                cpasync16(sbB + off, g_en + (size_t)(rowJ + r) * ND + kc + f * 4);
        }
        CP_COMMIT();
    };

    float acc[4][4][4];
    #pragma unroll
    for (int i = 0; i < 4; i++)
        #pragma unroll
        for (int j = 0; j < 4; j++)
            #pragma unroll
            for (int c = 0; c < 4; c++) acc[i][j][c] = 0.f;

    issue(0); issue(1);

    for (int g = 0; g < 8; g++) {
        if (g < 7) CP_WAIT1();
        else       CP_WAIT0();
        __syncthreads();                     // all warps done with chunk g-1
        if (g + 2 < 8) issue(g + 2);

        const int stage = g % NSTAGE;
        const float* Apan = OpA + stage * 128 * 32;
        const float* Bpan = diag ? Apan : OpB + stage * 128 * 32;
        #pragma unroll
        for (int ks = 0; ks < 4; ks++) {
            // fragment pair (k+qcol, k+qcol+4) sits at permuted position
            // ks*8 + 2*qcol (then XOR row swizzle) => one LDS.64.
            const int pos = (ks * 8 + 2 * qcol) ^ rsw;
            unsigned a[4][4], b[4][2];
            #pragma unroll
            for (int i = 0; i < 4; i++) {
                const int rl = warpM * 64 + i * 16 + qrow;
                float2 v0 = *reinterpret_cast<const float2*>(Apan + rl * 32 + pos);
                float2 v1 = *reinterpret_cast<const float2*>(Apan + (rl + 8) * 32 + pos);
                a[i][0] = __float_as_uint(v0.x);
                a[i][1] = __float_as_uint(v1.x);
                a[i][2] = __float_as_uint(v0.y);
                a[i][3] = __float_as_uint(v1.y);
            }
            #pragma unroll
            for (int j = 0; j < 4; j++) {
                const int rn = warpN * 32 + j * 8 + qrow;
                float2 v = *reinterpret_cast<const float2*>(Bpan + rn * 32 + pos);
                b[j][0] = __float_as_uint(v.x);
                b[j][1] = __float_as_uint(v.y);
            }
            #pragma unroll
            for (int i = 0; i < 4; i++)
                #pragma unroll
                for (int j = 0; j < 4; j++)
                    mma_tf32(acc[i][j], a[i], b[j]);
        }
    }
    __syncthreads();                         // GEMM done; operand smem now dead

    // ---- stage D into smem (stride 129) ----
    #pragma unroll
    for (int i = 0; i < 4; i++) {
        #pragma unroll
        for (int j = 0; j < 4; j++) {
            const int rl0 = warpM * 64 + i * 16 + qrow;
            const int cl0 = warpN * 32 + j * 8 + 2 * qcol;
            Ds[(size_t)rl0 * DST + cl0]           = acc[i][j][0];
            Ds[(size_t)rl0 * DST + cl0 + 1]       = acc[i][j][1];
            Ds[(size_t)(rl0 + 8) * DST + cl0]     = acc[i][j][2];
            Ds[(size_t)(rl0 + 8) * DST + cl0 + 1] = acc[i][j][3];
        }
    }
    __syncthreads();

    // ---- task-parallel epilogue: 512 tasks = {view, half, idx} ----
    const int rounds = diag ? 1 : 2;
    for (int rr = 0; rr < rounds; rr++) {
        const int tau  = tid + rr * 256;
        const int view = tau >> 8;
        const int half = (tau >> 7) & 1;
        const int idx  = tau & 127;
        float sA = 0.f, sP = 0.f, pm = NEGINF;
        float t0 = NEGINF, t1 = NEGINF, t2 = NEGINF;
        if (view == 0) {
            const int lr = labI[idx];
            const float* dr = Ds + (size_t)idx * DST + half * 64;
            #pragma unroll 4
            for (int c = 0; c < 64; c++) {
                float d = dr[c];
                const int col = half * 64 + c;
                if (!(diag && col == idx)) {
                    float E = ex2f(d * CEXP);
                    sA += E;
                    if (lr == labJ[col]) { sP += E; pm = fmaxf(pm, d); }
                    else ins3(t0, t1, t2, d);
                }
            }
        } else {
            const int lc = labJ[idx];
            #pragma unroll 4
            for (int r = 0; r < 64; r++) {
                float d = Ds[(size_t)(half * 64 + r) * DST + idx];
                float E = ex2f(d * CEXP);
                if (lc == labI[half * 64 + r]) { sA += E; sP += E; pm = fmaxf(pm, d); }
                else { sA += E; ins3(t0, t1, t2, d); }
            }
        }
        float* p = stg + (size_t)tau * 6;
        p[0] = sA; p[1] = sP; p[2] = pm; p[3] = t0; p[4] = t1; p[5] = t2;
    }
    __syncthreads();

    // ---- merge halves and write g_part ----
    if (tid < 128 || !diag) {
        const int view = tid >> 7;
        const int idx  = tid & 127;
        const float* p0 = stg + (size_t)(view * 256 + idx) * 6;
        const float* p1 = p0 + 128 * 6;
        float sA = p0[0] + p1[0];
        float sP = p0[1] + p1[1];
        float pm = fmaxf(p0[2], p1[2]);
        float t0 = p0[3], t1 = p0[4], t2 = p0[5];
        ins3(t0, t1, t2, p1[3]); ins3(t0, t1, t2, p1[4]); ins3(t0, t1, t2, p1[5]);
        const int slot = view ? I : J;
        const int grow = (view ? rowJ : rowI) + idx;
        g_part[(size_t)(0 * NBLK + slot) * NB + grow] = sA;
        g_part[(size_t)(1 * NBLK + slot) * NB + grow] = sP;
        g_part[(size_t)(2 * NBLK + slot) * NB + grow] = pm;
        g_part[(size_t)(3 * NBLK + slot) * NB + grow] = t0;
        g_part[(size_t)(4 * NBLK + slot) * NB + grow] = t1;
        g_part[(size_t)(5 * NBLK + slot) * NB + grow] = t2;
    }
}

// ---------------------------------------------------------------------------
// Kernel 3: per-row merge of 64 slot partials (8 threads/row) + loss terms,
// block-reduce to g_blk; LAST block does the final scalar (fused kfin).
// ---------------------------------------------------------------------------
__global__ void krow(float* __restrict__ out, int n) {
    const int gid = blockIdx.x * blockDim.x + threadIdx.x;
    const int row = gid >> 3;
    const int sl  = (gid & 7) * 8;
    float sA = 0.f, sP = 0.f, pm = NEGINF;
    float t0 = NEGINF, t1 = NEGINF, t2 = NEGINF;
    #pragma unroll
    for (int s = 0; s < 8; s++) {
        const int slot = sl + s;
        sA += g_part[(size_t)(0 * NBLK + slot) * NB + row];
        sP += g_part[(size_t)(1 * NBLK + slot) * NB + row];
        pm  = fmaxf(pm, g_part[(size_t)(2 * NBLK + slot) * NB + row]);
        ins3(t0, t1, t2, g_part[(size_t)(3 * NBLK + slot) * NB + row]);
        ins3(t0, t1, t2, g_part[(size_t)(4 * NBLK + slot) * NB + row]);
        ins3(t0, t1, t2, g_part[(size_t)(5 * NBLK + slot) * NB + row]);
    }
    #pragma unroll
    for (int o = 1; o <= 4; o <<= 1) {
        sA += __shfl_xor_sync(0xffffffffu, sA, o);
        sP += __shfl_xor_sync(0xffffffffu, sP, o);
        pm  = fmaxf(pm, __shfl_xor_sync(0xffffffffu, pm, o));
        float o0 = __shfl_xor_sync(0xffffffffu, t0, o);
        float o1 = __shfl_xor_sync(0xffffffffu, t1, o);
        float o2 = __shfl_xor_sync(0xffffffffu, t2, o);
        ins3(t0, t1, t2, o0); ins3(t0, t1, t2, o1); ins3(t0, t1, t2, o2);
    }

    float basic = 0.f, h = 0.f, m = 0.f, hp = 0.f, v = 0.f;
    if ((threadIdx.x & 7) == 0 && pm > -1e29f) {
        hp = 1.f;
        basic = -logf(sP / (sA + 1e-10f) + 1e-10f);
        float pms   = pm * (1.f / TEMP);
        float mean3 = (t0 + t1 + t2) * (1.f / (3.f * TEMP));
        h = fmaxf(mean3 - pms + MRG, 0.f);
        if (t0 > -1e29f) {
            v = 1.f;
            m = fmaxf(t0 * (1.f / TEMP) - pms + MRG, 0.f);
        }
    }

    __shared__ float red[5][8];
    float vals[5] = {basic, h, m, hp, v};
    int lane = threadIdx.x & 31, warp = threadIdx.x >> 5;
    #pragma unroll
    for (int q = 0; q < 5; q++) {
        float x = vals[q];
        #pragma unroll
        for (int o = 16; o > 0; o >>= 1) x += __shfl_xor_sync(0xffffffffu, x, o);
        if (lane == 0) red[q][warp] = x;
    }
    __syncthreads();
    if (warp == 0 && lane == 0) {
        #pragma unroll
        for (int q = 0; q < 5; q++) {
            float x = 0.f;
            #pragma unroll
            for (int w = 0; w < 8; w++) x += red[q][w];
            g_blk[blockIdx.x * 5 + q] = x;
        }
    }

    // ---- last-block final reduction (fused kfin) ----
    __shared__ bool s_last;
    if (threadIdx.x == 0) {
        __threadfence();
        unsigned t = atomicAdd(&g_ctr, 1u);
        s_last = (t == (unsigned)(RED_BLOCKS - 1));
    }
    __syncthreads();
    if (!s_last) return;
    __threadfence();

    float acc2[5];
    #pragma unroll
    for (int q = 0; q < 5; q++) acc2[q] = g_blk[threadIdx.x * 5 + q];
    __shared__ float fred[5][8];
    #pragma unroll
    for (int q = 0; q < 5; q++) {
        float x = acc2[q];
        #pragma unroll
        for (int o = 16; o > 0; o >>= 1) x += __shfl_xor_sync(0xffffffffu, x, o);
        if (lane == 0) fred[q][warp] = x;
    }
    __syncthreads();
    if (threadIdx.x == 0) {
        float tot[5];
        #pragma unroll
        for (int q = 0; q < 5; q++) {
            float x = 0.f;
            #pragma unroll
            for (int w = 0; w < 8; w++) x += fred[q][w];
            tot[q] = x;
        }
        float n_hp = fmaxf(tot[3], 1.f);
        float n_v  = fmaxf(tot[4], 1.f);
        float margin_loss = (tot[4] > 0.f) ? (tot[2] / n_v) : 0.f;
        float total = tot[0] / n_hp + 0.5f * (tot[1] / n_hp) + 0.1f * margin_loss;
        for (int i = 0; i < n; i++) out[i] = total;
    }
}

// ---------------------------------------------------------------------------
extern "C" void kernel_launch(void* const* d_in, const int* in_sizes, int n_in,
                              void* d_out, int out_size) {
    const float* emb   = (const float*)d_in[0];
    const int*   lab32 = (const int*)d_in[1];
    (void)in_sizes; (void)n_in;

    cudaFuncSetAttribute(kmain, cudaFuncAttributeMaxDynamicSharedMemorySize, SMEM_TOTAL);

    knorm<<<NB * 32 / 256 + 1, 256>>>(emb, lab32);   // +1 CTA: label detect + ctr reset
    kmain<<<NPAIR, NTHR, SMEM_TOTAL>>>();
    krow<<<RED_BLOCKS, 256>>>((float*)d_out, out_size);
}